// round 14
// baseline (speedup 1.0000x reference)
#include <cuda_runtime.h>
#include <cstdint>

#define N_CLASSES 2
#define N_FEATURES 100
#define DIM 10

#define BLOCK      128
#define TILE_ROWS  128
#define F4         25                       // float4 chunks per row
#define TILE_FLOATS (TILE_ROWS * N_FEATURES)   // 12800
#define TILE_BYTES  (TILE_FLOATS * 4)          // 51200
#define GRID       296                      // 2 blocks/SM, one wave

// Precomputed bilinear form Re(M)[k,a]  (2 x 100 floats).
__device__ float g_Mr[N_CLASSES * N_FEATURES];

// ---------------------------------------------------------------------------
// Kernel 1: one block per output element (k,a), 200 blocks.
__global__ void compute_M_kernel(const float* __restrict__ A_re,
                                 const float* __restrict__ A_im,
                                 const float* __restrict__ psi_re,
                                 const float* __restrict__ psi_im) {
    const int k = blockIdx.x / N_FEATURES;
    const int a = blockIdx.x % N_FEATURES;
    const int tid = threadIdx.x;          // 128 threads

    __shared__ float warp_sum[4];

    float s = 0.0f;
    if (tid < DIM * DIM) {
        int i = tid / DIM, j = tid % DIM;
        float pri = psi_re[i], pii = psi_im[i];
        float prj = psi_re[j], pij = psi_im[j];
        float wr = pri * prj + pii * pij;
        float wi = pri * pij - pii * prj;
        size_t off = ((size_t)k * DIM * DIM + tid) * N_FEATURES + a;
        s = A_re[off] * wr - A_im[off] * wi;
    }
    #pragma unroll
    for (int o = 16; o > 0; o >>= 1) s += __shfl_xor_sync(0xFFFFFFFF, s, o);
    if ((tid & 31) == 0) warp_sum[tid >> 5] = s;
    __syncthreads();
    if (tid == 0)
        g_Mr[blockIdx.x] = warp_sum[0] + warp_sum[1] + warp_sum[2] + warp_sum[3];
}

// ---------------------------------------------------------------------------
__device__ __forceinline__ void mbar_init(unsigned int mbar, unsigned int count) {
    asm volatile("mbarrier.init.shared.b64 [%0], %1;" :: "r"(mbar), "r"(count) : "memory");
}
__device__ __forceinline__ void mbar_expect_tx(unsigned int mbar, unsigned int bytes) {
    asm volatile("mbarrier.arrive.expect_tx.shared.b64 _, [%0], %1;"
                 :: "r"(mbar), "r"(bytes) : "memory");
}
__device__ __forceinline__ void mbar_wait_parity(unsigned int mbar, unsigned int parity) {
    asm volatile(
        "{\n\t"
        ".reg .pred P1;\n\t"
        "WAIT_LOOP_%=:\n\t"
        "mbarrier.try_wait.parity.acquire.cta.shared::cta.b64 P1, [%0], %1, 0x989680;\n\t"
        "@P1 bra.uni WAIT_DONE_%=;\n\t"
        "bra.uni WAIT_LOOP_%=;\n\t"
        "WAIT_DONE_%=:\n\t"
        "}"
        :: "r"(mbar), "r"(parity) : "memory");
}
__device__ __forceinline__ void bulk_copy_g2s(unsigned int dst_smem,
                                              const void* gsrc,
                                              unsigned int bytes,
                                              unsigned int mbar) {
    asm volatile(
        "cp.async.bulk.shared::cluster.global.mbarrier::complete_tx::bytes "
        "[%0], [%1], %2, [%3];"
        :: "r"(dst_smem), "l"(gsrc), "r"(bytes), "r"(mbar) : "memory");
}
__device__ __forceinline__ void fence_proxy_async_cta() {
    asm volatile("fence.proxy.async.shared::cta;" ::: "memory");
}

// Kernel 2: persistent blocks (2/SM), double-buffered cp.async.bulk pipeline.
// One UBLKCP per tile (issued by thread 0, completion via mbarrier expect_tx).
// Unpadded smem rows: stride 25 float4s (odd) => conflict-free LDS.128.
__global__ __launch_bounds__(BLOCK) void gemv_kernel(const float* __restrict__ x,
                                                     float2* __restrict__ out,
                                                     int ntiles) {
    extern __shared__ float smem[];
    // Layout: [0,16) two mbarriers, [16, 816) M, [816, ...) two tile buffers.
    unsigned int smem_base = (unsigned int)__cvta_generic_to_shared(smem);
    unsigned int mbar[2] = { smem_base, smem_base + 8 };
    float* msh = smem + 4;                         // 2*N_FEATURES floats
    float* buf[2] = { smem + 204, smem + 204 + TILE_FLOATS };
    unsigned int buf_u32[2] = {
        (unsigned int)__cvta_generic_to_shared(buf[0]),
        (unsigned int)__cvta_generic_to_shared(buf[1]) };

    const int tid = threadIdx.x;

    if (tid == 0) {
        mbar_init(mbar[0], 1);
        mbar_init(mbar[1], 1);
    }
    // Stage M into smem (50 float4 chunks).
    if (tid < (2 * N_FEATURES) / 4) {
        reinterpret_cast<float4*>(msh)[tid] =
            reinterpret_cast<const float4*>(g_Mr)[tid];
    }
    __syncthreads();
    fence_proxy_async_cta();   // make mbarrier init visible to the async proxy

    const int stride = gridDim.x;
    int tile = blockIdx.x;
    if (tile >= ntiles) return;

    // Prologue: start streaming first tile into buffer 0.
    if (tid == 0) {
        mbar_expect_tx(mbar[0], TILE_BYTES);
        bulk_copy_g2s(buf_u32[0], x + (size_t)tile * TILE_FLOATS, TILE_BYTES, mbar[0]);
    }

    unsigned int phase[2] = { 0, 0 };
    int b = 0;
    for (; tile < ntiles; tile += stride, b ^= 1) {
        int next = tile + stride;
        if (next < ntiles && tid == 0) {
            // buf[b^1] was released by last iteration's trailing __syncthreads.
            mbar_expect_tx(mbar[b ^ 1], TILE_BYTES);
            bulk_copy_g2s(buf_u32[b ^ 1], x + (size_t)next * TILE_FLOATS,
                          TILE_BYTES, mbar[b ^ 1]);
        }

        mbar_wait_parity(mbar[b], phase[b]);
        phase[b] ^= 1;

        // Compute: thread t -> row t of this tile (row stride 25 float4s).
        {
            const float4* xr = reinterpret_cast<const float4*>(buf[b]) + tid * F4;
            const float4* m0 = reinterpret_cast<const float4*>(msh);
            const float4* m1 = reinterpret_cast<const float4*>(msh + N_FEATURES);
            float a = 0.0f, c = 0.0f;
            #pragma unroll
            for (int i = 0; i < F4; i++) {
                float4 xv = xr[i];
                float4 u = m0[i];
                float4 v = m1[i];
                a += xv.x * u.x + xv.y * u.y + xv.z * u.z + xv.w * u.w;
                c += xv.x * v.x + xv.y * v.y + xv.z * v.z + xv.w * v.w;
            }
            out[tile * TILE_ROWS + tid] = make_float2(a, c);
        }
        __syncthreads();   // all reads of buf[b] done before it is refilled
    }
}

// ---------------------------------------------------------------------------
extern "C" void kernel_launch(void* const* d_in, const int* in_sizes, int n_in,
                              void* d_out, int out_size) {
    const float* x      = (const float*)d_in[0];
    const float* A_re   = (const float*)d_in[1];
    const float* A_im   = (const float*)d_in[2];
    const float* psi_re = (const float*)d_in[3];
    const float* psi_im = (const float*)d_in[4];
    float2* out = (float2*)d_out;

    int T = in_sizes[0] / N_FEATURES;   // 262144
    int ntiles = T / TILE_ROWS;         // 2048 (T is a multiple of 128)

    compute_M_kernel<<<N_CLASSES * N_FEATURES, 128>>>(A_re, A_im, psi_re, psi_im);

    // 16 B mbarriers + 800 B M + 2 x 51200 B buffers
    const int smem_bytes = 16 + 2 * N_FEATURES * 4 + 2 * TILE_BYTES;  // 103216
    cudaFuncSetAttribute(gemv_kernel,
                         cudaFuncAttributeMaxDynamicSharedMemorySize, smem_bytes);

    gemv_kernel<<<GRID, BLOCK, smem_bytes>>>(x, out, ntiles);
}